// round 2
// baseline (speedup 1.0000x reference)
#include <cuda_runtime.h>
#include <math.h>

#define BB 1024
#define TT 80
#define EE 100
#define EP 112      // E padded to multiple of 4 floats (16B) for float4 loads
#define UU 256

// ---------------- device scratch (no allocations allowed) ----------------
__device__ float g_X[(size_t)TT * BB * EP];   // [t][b][e], zero-padded e>=100
__device__ float g_h1[2][BB * UU];
__device__ float g_c1[BB * UU];
__device__ float g_h2[2][BB * UU];
__device__ float g_c2[BB * UU];

// ---------------- init: embedding gather + zero states ----------------
__global__ void init_kernel(const int* __restrict__ tokens,
                            const float* __restrict__ emb) {
    int idx = blockIdx.x * 256 + threadIdx.x;
    if (idx < TT * BB * EP) {
        int e  = idx % EP;
        int tb = idx / EP;
        int b  = tb % BB;
        int t  = tb / BB;
        float v = 0.0f;
        if (e < EE) {
            int tok = tokens[b * TT + t];
            v = emb[(size_t)tok * EE + e];
        }
        g_X[idx] = v;
    }
    if (idx < BB * UU) {
        g_h1[0][idx] = 0.0f;
        g_c1[idx]    = 0.0f;
        g_h2[0][idx] = 0.0f;
        g_c2[idx]    = 0.0f;
    }
}

// ---------------- fused LSTM step (one layer) ----------------
// Computes all 4 gates for a 64x32 (batch x unit) tile, then the cell update.
// hx = concat([h, x]) along dim: rows 0..255 of W multiply h, rows 256.. multiply x.
// DX = padded x width (112 for layer1, 256 for layer2). Dvalid = real W rows.
template <int DX>
__global__ __launch_bounds__(256)
void lstm_step(const float* __restrict__ h_in,
               float* __restrict__ h_out,
               float* __restrict__ c_st,
               const float* __restrict__ x,    // [B, DX]
               const float* __restrict__ Wf, const float* __restrict__ Wi,
               const float* __restrict__ Wc, const float* __restrict__ Wo,
               const float* __restrict__ bf, const float* __restrict__ bi,
               const float* __restrict__ bc, const float* __restrict__ bo,
               int Dvalid) {
    __shared__ float As[16][64];        // hx tile, [k][m]
    __shared__ float Ws[4][16][32];     // weight tiles per gate, [g][k][n]

    const int tid = threadIdx.x;
    const int b0  = blockIdx.x * 64;
    const int n0  = blockIdx.y * 32;

    const int tm = tid >> 4;            // 0..15 -> 4 batch rows each
    const int tn = tid & 15;            // 0..15 -> 2 unit cols each

    // A-loader: each thread loads 4 consecutive k for one batch row (float4)
    const int am = tid & 63;            // m within tile
    const int ak = (tid >> 6) * 4;      // k offset within tile: 0,4,8,12

    // W-loader: each thread loads (wk, wk+8) x 1 col per gate
    const int wn = tid & 31;
    const int wk = tid >> 5;            // 0..7

    const float* Wp[4] = {Wf, Wi, Wc, Wo};

    float acc[4][4][2];
#pragma unroll
    for (int g = 0; g < 4; g++)
#pragma unroll
        for (int i = 0; i < 4; i++) { acc[g][i][0] = 0.0f; acc[g][i][1] = 0.0f; }

    const int NK = (UU + DX) / 16;      // 23 (layer1) or 32 (layer2)

    for (int kt = 0; kt < NK; kt++) {
        const int k0 = kt * 16;
        // ---- load A tile (hx) ----
        {
            const int k = k0 + ak;
            float4 v;
            if (k < UU) {
                v = *(const float4*)&h_in[(b0 + am) * UU + k];
            } else {
                v = *(const float4*)&x[(size_t)(b0 + am) * DX + (k - UU)];
            }
            As[ak + 0][am] = v.x;
            As[ak + 1][am] = v.y;
            As[ak + 2][am] = v.z;
            As[ak + 3][am] = v.w;
        }
        // ---- load W tiles (4 gates) ----
#pragma unroll
        for (int g = 0; g < 4; g++) {
#pragma unroll
            for (int h = 0; h < 2; h++) {
                int k   = k0 + wk + h * 8;
                int row = (k < Dvalid) ? k : (Dvalid - 1);  // pad rows hit As==0
                Ws[g][wk + h * 8][wn] = Wp[g][(size_t)row * UU + n0 + wn];
            }
        }
        __syncthreads();

        // ---- FMA inner loop ----
#pragma unroll
        for (int kk = 0; kk < 16; kk++) {
            float4 a = *(const float4*)&As[kk][tm * 4];
#pragma unroll
            for (int g = 0; g < 4; g++) {
                float2 w = *(const float2*)&Ws[g][kk][tn * 2];
                acc[g][0][0] += a.x * w.x;  acc[g][0][1] += a.x * w.y;
                acc[g][1][0] += a.y * w.x;  acc[g][1][1] += a.y * w.y;
                acc[g][2][0] += a.z * w.x;  acc[g][2][1] += a.z * w.y;
                acc[g][3][0] += a.w * w.x;  acc[g][3][1] += a.w * w.y;
            }
        }
        __syncthreads();
    }

    // ---- LSTM cell epilogue ----
#pragma unroll
    for (int mi = 0; mi < 4; mi++) {
        const int b = b0 + tm * 4 + mi;
#pragma unroll
        for (int ni = 0; ni < 2; ni++) {
            const int u = n0 + tn * 2 + ni;
            float gf = acc[0][mi][ni] + bf[u];
            float gi = acc[1][mi][ni] + bi[u];
            float gc = acc[2][mi][ni] + bc[u];
            float go = acc[3][mi][ni] + bo[u];
            float sf = 1.0f / (1.0f + expf(-gf));
            float si = 1.0f / (1.0f + expf(-gi));
            float so = 1.0f / (1.0f + expf(-go));
            float ct = tanhf(gc);
            float cn = sf * c_st[b * UU + u] + si * ct;
            c_st[b * UU + u]  = cn;
            h_out[b * UU + u] = so * tanhf(cn);
        }
    }
}

// ---------------- output head: sigmoid(h2 @ w_out + b_out) ----------------
__global__ void final_kernel(const float* __restrict__ h2,
                             const float* __restrict__ w_out,
                             const float* __restrict__ b_out,
                             float* __restrict__ out) {
    int b    = blockIdx.x * 8 + (threadIdx.x >> 5);
    int lane = threadIdx.x & 31;
    float s = 0.0f;
#pragma unroll
    for (int u = lane; u < UU; u += 32) s += h2[b * UU + u] * w_out[u];
#pragma unroll
    for (int off = 16; off; off >>= 1) s += __shfl_xor_sync(0xFFFFFFFFu, s, off);
    if (lane == 0) out[b] = 1.0f / (1.0f + expf(-(s + b_out[0])));
}

// ---------------- launch ----------------
extern "C" void kernel_launch(void* const* d_in, const int* in_sizes, int n_in,
                              void* d_out, int out_size) {
    const int*   tokens = (const int*)d_in[0];
    const float* emb    = (const float*)d_in[1];
    const float* wf1 = (const float*)d_in[2];  const float* bf1 = (const float*)d_in[3];
    const float* wi1 = (const float*)d_in[4];  const float* bi1 = (const float*)d_in[5];
    const float* wc1 = (const float*)d_in[6];  const float* bc1 = (const float*)d_in[7];
    const float* wo1 = (const float*)d_in[8];  const float* bo1 = (const float*)d_in[9];
    const float* wf2 = (const float*)d_in[10]; const float* bf2 = (const float*)d_in[11];
    const float* wi2 = (const float*)d_in[12]; const float* bi2 = (const float*)d_in[13];
    const float* wc2 = (const float*)d_in[14]; const float* bc2 = (const float*)d_in[15];
    const float* wo2 = (const float*)d_in[16]; const float* bo2 = (const float*)d_in[17];
    const float* w_out = (const float*)d_in[18];
    const float* b_out = (const float*)d_in[19];
    float* out = (float*)d_out;

    float *pX, *ph1, *pc1, *ph2, *pc2;
    cudaGetSymbolAddress((void**)&pX,  g_X);
    cudaGetSymbolAddress((void**)&ph1, g_h1);
    cudaGetSymbolAddress((void**)&pc1, g_c1);
    cudaGetSymbolAddress((void**)&ph2, g_h2);
    cudaGetSymbolAddress((void**)&pc2, g_c2);

    // init: gather embeddings (padded) + zero states
    {
        int total = TT * BB * EP;
        init_kernel<<<(total + 255) / 256, 256>>>(tokens, emb);
    }

    dim3 gridS(BB / 64, UU / 32);   // 16 x 8 = 128 CTAs
    int p = 0;
    for (int t = 0; t < TT; t++) {
        const float* xt = pX + (size_t)t * BB * EP;
        // layer 1: hx = [h1, x_t]
        lstm_step<EP><<<gridS, 256>>>(
            ph1 + p * (BB * UU), ph1 + (1 - p) * (BB * UU), pc1, xt,
            wf1, wi1, wc1, wo1, bf1, bi1, bc1, bo1, UU + EE);
        // layer 2: hx = [h2, h1_new]
        lstm_step<UU><<<gridS, 256>>>(
            ph2 + p * (BB * UU), ph2 + (1 - p) * (BB * UU), pc2,
            ph1 + (1 - p) * (BB * UU),
            wf2, wi2, wc2, wo2, bf2, bi2, bc2, bo2, UU + UU);
        p ^= 1;
    }

    final_kernel<<<BB / 8, 256>>>(ph2 + p * (BB * UU), w_out, b_out, out);
}